// round 10
// baseline (speedup 1.0000x reference)
#include <cuda_runtime.h>

#define B_ 32
#define S_ 4096
#define H_ 1024
#define NSPANS_ 16
#define NCLS_ 25
#define H4_ (H_ / 4)      // 256 float4 per row
#define CHUNK_ 16         // tokens per pool block
#define NCHUNK_ 4         // ceil(63 / CHUNK_)
#define NFC1_ 128         // fc1 tiles (32 j-tiles x 4 b-groups)
#define KT_ 32            // K-tile rows per quarter per iteration
#define KQLEN_ (H_ / 4)   // 256 k-rows per quarter
#define NIT_ (KQLEN_ / KT_)  // 8 iterations

// Persistent scratch. Zero-initialized at load; the fc1 epilogue restores
// zeros at the end of every call, so each invocation sees identical state.
__device__ float g_pooled[B_ * H_];
__device__ float g_logits[B_ * NCLS_];
__device__ unsigned g_cnt;

__device__ __forceinline__ void f4add(float4& a, const float4 b) {
    a.x += b.x; a.y += b.y; a.z += b.z; a.w += b.w;
}

// ---------------------------------------------------------------------------
// Kernel 1: span gather-sum. grid (NCHUNK, NSPANS, B), block 256, tiny smem.
// Identical to round-9 winner + PDL trigger once this block's atomics are out.
// ---------------------------------------------------------------------------
__global__ void __launch_bounds__(256)
pool_kernel(const float* __restrict__ emb,
            const int* __restrict__ spans,
            float* __restrict__ pooled) {
    const int b = blockIdx.z;
    const int n = blockIdx.y;
    const int c = blockIdx.x;

    __shared__ int ss, se, svalid;
    if (threadIdx.x == 0) {
        const int* row = spans + b * (NSPANS_ * 2);
        int s = row[2 * n], e = row[2 * n + 1];
        int v = !(s == 0 && e == 0);
        for (int m = 0; m < n && v; m++) {           // torch 'break' semantics
            if (row[2 * m] == 0 && row[2 * m + 1] == 0) v = 0;
        }
        int cs = s + c * CHUNK_;
        int ce = cs + CHUNK_ < e ? cs + CHUNK_ : e;
        ss = cs; se = ce; svalid = v && (cs < e);
    }
    __syncthreads();

    if (svalid) {
        const int s = ss, e = se;
        const float4* base =
            (const float4*)emb + (size_t)b * S_ * H4_ + threadIdx.x;

        float4 a0 = {0,0,0,0}, a1 = {0,0,0,0}, a2 = {0,0,0,0}, a3 = {0,0,0,0};
        int t = s;
        for (; t + 3 < e; t += 4) {
            f4add(a0, base[(size_t)(t + 0) * H4_]);
            f4add(a1, base[(size_t)(t + 1) * H4_]);
            f4add(a2, base[(size_t)(t + 2) * H4_]);
            f4add(a3, base[(size_t)(t + 3) * H4_]);
        }
        for (; t < e; t++) f4add(a0, base[(size_t)t * H4_]);
        f4add(a0, a1); f4add(a2, a3); f4add(a0, a2);

        float* dst = pooled + b * H_ + threadIdx.x * 4;
        atomicAdd(dst + 0, a0.x);
        atomicAdd(dst + 1, a0.y);
        atomicAdd(dst + 2, a0.z);
        atomicAdd(dst + 3, a0.w);
    }

    // PDL: this block's contribution is globally visible; release fc1 launch.
    cudaTriggerProgrammaticLaunchCompletion();
}

// ---------------------------------------------------------------------------
// Kernel 2: fc1, 512 threads, 4-way split-K (identical math to round-9).
// Launched with programmatic stream serialization: the pool-independent
// prologue (span counts, W1 tile-0 fetch) runs concurrently with pool's tail;
// cudaGridDependencySynchronize() gates the first g_pooled read.
// ---------------------------------------------------------------------------
__global__ void __launch_bounds__(512)
fc1_kernel(const int* __restrict__ spans,
           const float* __restrict__ W1,
           const float* __restrict__ b1,
           const float* __restrict__ W2,
           const float* __restrict__ b2,
           float* __restrict__ out) {
    const int tile = blockIdx.x;
    const int bg = tile & 3;
    const int jt = tile >> 2;
    const int tid = threadIdx.x;
    const int lane = tid & 31;
    const int ty = tid >> 5;          // 0..15
    const int kq = ty & 3;            // k-quarter
    const int bp = ty >> 2;           // batch-pair 0..3
    const int j = jt * 32 + lane;

    __shared__ float wt[2][4][KT_][32];   // 32 KB W1 tiles (per quarter)
    __shared__ float pt[2][4][8][KT_];    // 8 KB pooled tiles (per quarter)
    __shared__ float redA[3][4][32], redB[3][4][32];  // 3 KB split-K exchange
    __shared__ float s_inv[8];
    __shared__ unsigned s_ticket;

    // ----- pool-independent prologue (overlaps with pool via PDL) -----------
    if (tid < 8) {
        const int* row = spans + (bg * 8 + tid) * (NSPANS_ * 2);
        int total = 0;
        #pragma unroll
        for (int m = 0; m < NSPANS_; m++) {
            int a = row[2 * m], e = row[2 * m + 1];
            if (a == 0 && e == 0) break;
            total += e - a;
        }
        s_inv[tid] = 1.0f / (float)total;
    }

    // W1: 4 quarters x 32 rows x 8 float4-cols = 1024 float4; 2 per thread.
    const int wq = tid >> 7;                   // quarter 0..3
    const int wr = (tid & 127) >> 2;           // k-row within tile 0..31
    const int wc = (tid & 3) * 8;              // float-col 0,8,16,24
    const float* wsrc =
        W1 + (size_t)(wq * KQLEN_ + wr) * H_ + jt * 32 + wc;
    // pooled: 4 quarters x 8 rows x 8 float4 = 256 float4; tid<256, 1 each.
    const int pq = (tid >> 6) & 3;
    const int pr = (tid >> 3) & 7;
    const int pc = (tid & 7) * 4;
    const float* psrc =
        g_pooled + (size_t)(bg * 8 + pr) * H_ + pq * KQLEN_ + pc;

    // W1 tile 0 fetch (independent of pool)
    float4 rw0 = *(const float4*)(wsrc);
    float4 rw1 = *(const float4*)(wsrc + 4);
    *(float4*)&wt[0][wq][wr][wc] = rw0;
    *(float4*)&wt[0][wq][wr][wc + 4] = rw1;

    // ----- wait for pool grid's writes to be visible ------------------------
    cudaGridDependencySynchronize();

    float4 rp;
    if (tid < 256) {
        rp = *(const float4*)(psrc);
        *(float4*)&pt[0][pq][pr][pc] = rp;
    }
    __syncthreads();

    float a0 = 0.f, a1 = 0.f, ba = 0.f, bb = 0.f;

    #pragma unroll 1
    for (int t = 0; t < NIT_; t++) {
        if (t + 1 < NIT_) {
            rw0 = *(const float4*)(wsrc + (size_t)(t + 1) * KT_ * H_);
            rw1 = *(const float4*)(wsrc + (size_t)(t + 1) * KT_ * H_ + 4);
            if (tid < 256) rp = *(const float4*)(psrc + (t + 1) * KT_);
        }

        const float* wk = &wt[t & 1][kq][0][lane];
        const float4* pa = (const float4*)&pt[t & 1][kq][2 * bp + 0][0];
        const float4* pb = (const float4*)&pt[t & 1][kq][2 * bp + 1][0];
        #pragma unroll
        for (int kk = 0; kk < 8; kk++) {
            const float4 x = pa[kk];
            const float4 y = pb[kk];
            const float w0 = wk[(4 * kk + 0) * 32];
            const float w1 = wk[(4 * kk + 1) * 32];
            const float w2 = wk[(4 * kk + 2) * 32];
            const float w3 = wk[(4 * kk + 3) * 32];
            a0 = fmaf(x.x, w0, a0); a1 = fmaf(x.y, w1, a1);
            ba = fmaf(y.x, w0, ba); bb = fmaf(y.y, w1, bb);
            a0 = fmaf(x.z, w2, a0); a1 = fmaf(x.w, w3, a1);
            ba = fmaf(y.z, w2, ba); bb = fmaf(y.w, w3, bb);
        }

        if (t + 1 < NIT_) {
            *(float4*)&wt[(t + 1) & 1][wq][wr][wc] = rw0;
            *(float4*)&wt[(t + 1) & 1][wq][wr][wc + 4] = rw1;
            if (tid < 256) *(float4*)&pt[(t + 1) & 1][pq][pr][pc] = rp;
        }
        __syncthreads();
    }
    float d0 = a0 + a1;    // batch 2bp   partial (this quarter)
    float d1 = ba + bb;    // batch 2bp+1 partial

    // close split-K
    if (kq != 0) {
        redA[kq - 1][bp][lane] = d0;
        redB[kq - 1][bp][lane] = d1;
    }
    __syncthreads();
    if (kq == 0) {
        d0 += redA[0][bp][lane] + redA[1][bp][lane] + redA[2][bp][lane];
        d1 += redB[0][bp][lane] + redB[1][bp][lane] + redB[2][bp][lane];
        const float bias = b1[j];
        const float h0 = fmaxf(fmaf(d0, s_inv[2 * bp + 0], bias), 0.f);
        const float h1 = fmaxf(fmaf(d1, s_inv[2 * bp + 1], bias), 0.f);

        // fc2 partial for 2 batches
        float acc0 = 0.f, acc1 = 0.f;
        const int jbase = jt * 32;
        #pragma unroll
        for (int l = 0; l < 32; l++) {
            const float hv0 = __shfl_sync(0xffffffffu, h0, l);
            const float hv1 = __shfl_sync(0xffffffffu, h1, l);
            if (lane < NCLS_) {
                const float wv = W2[(jbase + l) * NCLS_ + lane];
                acc0 = fmaf(hv0, wv, acc0);
                acc1 = fmaf(hv1, wv, acc1);
            }
        }
        if (lane < NCLS_) {
            const int brow0 = bg * 8 + 2 * bp;
            atomicAdd(g_logits + brow0 * NCLS_ + lane, acc0);
            atomicAdd(g_logits + (brow0 + 1) * NCLS_ + lane, acc1);
        }
    }

    // ---- ticket: the block drawing NFC1_-1 is provably last; no spin -------
    __threadfence();
    __syncthreads();
    if (tid == 0) s_ticket = atomicAdd(&g_cnt, 1u);
    __syncthreads();
    if (s_ticket != (unsigned)(NFC1_ - 1)) return;

    // ---- epilogue: sigmoid + restore zero state -----------------------------
    for (int idx = tid; idx < B_ * NCLS_; idx += 512) {
        const float v = __ldcg(g_logits + idx) + b2[idx % NCLS_];
        out[idx] = 1.f / (1.f + __expf(-v));
        g_logits[idx] = 0.f;
    }
    {
        float4* pz = (float4*)g_pooled;
        for (int k = tid; k < B_ * H4_; k += 512)
            pz[k] = make_float4(0.f, 0.f, 0.f, 0.f);
    }
    if (tid == 0) g_cnt = 0u;
}

// ---------------------------------------------------------------------------
extern "C" void kernel_launch(void* const* d_in, const int* in_sizes, int n_in,
                              void* d_out, int out_size) {
    const float* all_emb = (const float*)d_in[0];
    const int*   spans   = (const int*)d_in[1];
    const float* W1      = (const float*)d_in[2];
    const float* b1      = (const float*)d_in[3];
    const float* W2      = (const float*)d_in[4];
    const float* b2      = (const float*)d_in[5];
    float* out = (float*)d_out;

    float* pooled;
    cudaGetSymbolAddress((void**)&pooled, g_pooled);

    {
        dim3 grid(NCHUNK_, NSPANS_, B_);
        pool_kernel<<<grid, 256>>>(all_emb, spans, pooled);
    }
    {
        // fc1 with programmatic dependent launch: overlaps pool's tail.
        cudaLaunchConfig_t cfg = {};
        cfg.gridDim = dim3(NFC1_, 1, 1);
        cfg.blockDim = dim3(512, 1, 1);
        cfg.dynamicSmemBytes = 0;
        cfg.stream = 0;   // legacy default stream (same as <<<>>> above)
        cudaLaunchAttribute attrs[1];
        attrs[0].id = cudaLaunchAttributeProgrammaticStreamSerialization;
        attrs[0].val.programmaticStreamSerializationAllowed = 1;
        cfg.attrs = attrs;
        cfg.numAttrs = 1;
        cudaLaunchKernelEx(&cfg, fc1_kernel, spans, W1, b1, W2, b2, out);
    }
}